// round 1
// baseline (speedup 1.0000x reference)
#include <cuda_runtime.h>
#include <math.h>

#define GS    14
#define NQ    196            // GS*GS
#define CDIM  128
#define NH    4
#define HD    32
#define BATCH 1024
#define MTOT  (BATCH * NQ)   // 200704
#define KVN   384            // q(128) | k(128) | v(128)
#define TAB   729            // (2*GS-1)^2
#define SCALE 0.17677669529663688f   // 32^-0.5

// ---- scratch (static device allocations; no cudaMalloc allowed) ----
__device__ float g_qkv[(size_t)MTOT * KVN];   // ~308 MB
__device__ float g_att[(size_t)MTOT * CDIM];  // ~103 MB
__device__ float g_pos[TAB * NH];             // pos-bias MLP table

// ============================================================
// Kernel 1: dynamic position-bias MLP (729 rows, tiny)
// ============================================================
__device__ __forceinline__ void ln_relu8(float* x, const float* g, const float* b) {
    float mu = 0.f;
#pragma unroll
    for (int d = 0; d < 8; d++) mu += x[d];
    mu *= 0.125f;
    float var = 0.f;
#pragma unroll
    for (int d = 0; d < 8; d++) { float t = x[d] - mu; var += t * t; }
    var *= 0.125f;
    float inv = rsqrtf(var + 1e-5f);
#pragma unroll
    for (int d = 0; d < 8; d++) {
        float t = (x[d] - mu) * inv * g[d] + b[d];
        x[d] = t > 0.f ? t : 0.f;
    }
}

__global__ void pos_mlp_kernel(
    const float* __restrict__ pp_w, const float* __restrict__ pp_b,
    const float* __restrict__ ln1_g, const float* __restrict__ ln1_b,
    const float* __restrict__ l1_w,  const float* __restrict__ l1_b,
    const float* __restrict__ ln2_g, const float* __restrict__ ln2_b,
    const float* __restrict__ l2_w,  const float* __restrict__ l2_b,
    const float* __restrict__ ln3_g, const float* __restrict__ ln3_b,
    const float* __restrict__ l3_w,  const float* __restrict__ l3_b)
{
    int m = blockIdx.x * blockDim.x + threadIdx.x;
    if (m >= TAB) return;
    float bi = (float)(m / 27 - 13);
    float bj = (float)(m % 27 - 13);
    float h[8], t[8];
#pragma unroll
    for (int d = 0; d < 8; d++) h[d] = bi * pp_w[d] + bj * pp_w[8 + d] + pp_b[d];
    ln_relu8(h, ln1_g, ln1_b);
#pragma unroll
    for (int j = 0; j < 8; j++) {
        float a = l1_b[j];
#pragma unroll
        for (int d = 0; d < 8; d++) a += h[d] * l1_w[d * 8 + j];
        t[j] = a;
    }
    ln_relu8(t, ln2_g, ln2_b);
#pragma unroll
    for (int j = 0; j < 8; j++) {
        float a = l2_b[j];
#pragma unroll
        for (int d = 0; d < 8; d++) a += t[d] * l2_w[d * 8 + j];
        h[j] = a;
    }
    ln_relu8(h, ln3_g, ln3_b);
#pragma unroll
    for (int j = 0; j < NH; j++) {
        float a = l3_b[j];
#pragma unroll
        for (int d = 0; d < 8; d++) a += h[d] * l3_w[d * NH + j];
        g_pos[m * NH + j] = a;
    }
}

// ============================================================
// Kernel 2: fused QKV GEMM  [200704,128] x [128,384] -> g_qkv
//   cols 0..127  = x @ wq
//   cols 128..383 = x @ wkv   (k = 128..255, v = 256..383)
// ============================================================
#define BM 128
#define BN 64
#define BK 16

__global__ __launch_bounds__(256) void qkv_gemm_kernel(
    const float* __restrict__ x,
    const float* __restrict__ wq,
    const float* __restrict__ wkv)
{
    __shared__ float As[BK][BM];
    __shared__ float Bs[BK][BN];

    const int m0 = blockIdx.x * BM;
    const int j0 = blockIdx.y * BN;
    const int tid = threadIdx.x;
    const int ty = tid >> 4;     // 0..15 -> 8 rows each
    const int tx = tid & 15;     // 0..15 -> 4 cols each

    const float* wsrc; int ldw, c0;
    if (j0 < 128) { wsrc = wq;  ldw = 128; c0 = j0; }
    else          { wsrc = wkv; ldw = 256; c0 = j0 - 128; }

    float acc[8][4];
#pragma unroll
    for (int i = 0; i < 8; i++)
#pragma unroll
        for (int j = 0; j < 4; j++) acc[i][j] = 0.f;

    for (int k0 = 0; k0 < CDIM; k0 += BK) {
        // load A tile (transposed into As[k][m]); 512 float4 total, 2 per thread
#pragma unroll
        for (int p = tid; p < (BM * BK) / 4; p += 256) {
            int row = p >> 2, kq = p & 3;
            float4 v = *(const float4*)&x[(size_t)(m0 + row) * CDIM + k0 + kq * 4];
            As[kq * 4 + 0][row] = v.x;
            As[kq * 4 + 1][row] = v.y;
            As[kq * 4 + 2][row] = v.z;
            As[kq * 4 + 3][row] = v.w;
        }
        // load B tile; 256 float4 total, 1 per thread
        {
            int kk = tid >> 4, j4 = tid & 15;
            float4 v = *(const float4*)&wsrc[(size_t)(k0 + kk) * ldw + c0 + j4 * 4];
            *(float4*)&Bs[kk][j4 * 4] = v;
        }
        __syncthreads();
#pragma unroll
        for (int kk = 0; kk < BK; kk++) {
            float4 a0 = *(const float4*)&As[kk][ty * 8];
            float4 a1 = *(const float4*)&As[kk][ty * 8 + 4];
            float4 bv = *(const float4*)&Bs[kk][tx * 4];
            float a[8] = {a0.x, a0.y, a0.z, a0.w, a1.x, a1.y, a1.z, a1.w};
            float bb[4] = {bv.x, bv.y, bv.z, bv.w};
#pragma unroll
            for (int i = 0; i < 8; i++)
#pragma unroll
                for (int j = 0; j < 4; j++) acc[i][j] += a[i] * bb[j];
        }
        __syncthreads();
    }
#pragma unroll
    for (int i = 0; i < 8; i++) {
        float4 o = make_float4(acc[i][0], acc[i][1], acc[i][2], acc[i][3]);
        *(float4*)&g_qkv[(size_t)(m0 + ty * 8 + i) * KVN + j0 + tx * 4] = o;
    }
}

// ============================================================
// Kernel 3: attention per (batch, head) CTA
//   scores = qk^T*scale + bias -> softmax -> @ v  -> g_att
// ============================================================
#define KPAD 33   // 32+1 pad: conflict-free for both row-dot and dim-per-lane access
#define SM_Q   0
#define SM_K   (NQ * KPAD)
#define SM_V   (2 * NQ * KPAD)
#define SM_POS (3 * NQ * KPAD)
#define SM_PRB (3 * NQ * KPAD + TAB * NH)
#define SMEM_ATTN_FLOATS (3 * NQ * KPAD + TAB * NH + 16 * NQ)
#define SMEM_ATTN_BYTES  (SMEM_ATTN_FLOATS * 4)

__global__ __launch_bounds__(256, 2) void attn_kernel()
{
    extern __shared__ float sm[];
    float* sq   = sm + SM_Q;
    float* sk   = sm + SM_K;
    float* sv   = sm + SM_V;
    float* spos = sm + SM_POS;
    float* sprb = sm + SM_PRB;

    const int b = blockIdx.x;
    const int h = blockIdx.y;
    const int tid = threadIdx.x;

    // stage q/k/v for this (b,h) + the pos table
    const float* base = g_qkv + (size_t)b * NQ * KVN + h * HD;
    for (int idx = tid; idx < NQ * HD; idx += 256) {
        int n = idx >> 5, d = idx & 31;
        const float* row = base + (size_t)n * KVN;
        sq[n * KPAD + d] = row[d];
        sk[n * KPAD + d] = row[128 + d];
        sv[n * KPAD + d] = row[256 + d];
    }
    for (int idx = tid; idx < TAB * NH; idx += 256) spos[idx] = g_pos[idx];
    __syncthreads();

    const int w = tid >> 5, lane = tid & 31;

    // each warp handles query-row pairs (r0, r0+1); TQ=2 halves smem traffic
    for (int r0 = w * 2; r0 < NQ; r0 += 16) {
        const int r1 = r0 + 1;
        const int qi0 = r0 / GS, qj0 = r0 - qi0 * GS;
        const int qi1 = r1 / GS, qj1 = r1 - qi1 * GS;

        float q0[HD], q1[HD];
#pragma unroll
        for (int d = 0; d < HD; d++) {
            q0[d] = sq[r0 * KPAD + d];
            q1[d] = sq[r1 * KPAD + d];
        }

        float s0[7], s1[7];
        float mx0 = -1e30f, mx1 = -1e30f;
        int cnt = 0;
        for (int kk = lane; kk < NQ; kk += 32) {
            const float* kr = sk + kk * KPAD;
            float a = 0.f, c = 0.f;
#pragma unroll
            for (int d = 0; d < HD; d++) {
                float kv = kr[d];
                a += q0[d] * kv;
                c += q1[d] * kv;
            }
            int ki = kk / GS, kj = kk - ki * GS;
            int pbase0 = ((qi0 - ki + GS - 1) * (2 * GS - 1) + (qj0 - kj + GS - 1)) * NH + h;
            int pbase1 = ((qi1 - ki + GS - 1) * (2 * GS - 1) + (qj1 - kj + GS - 1)) * NH + h;
            a = a * SCALE + spos[pbase0];
            c = c * SCALE + spos[pbase1];
            s0[cnt] = a; s1[cnt] = c; cnt++;
            mx0 = fmaxf(mx0, a);
            mx1 = fmaxf(mx1, c);
        }
#pragma unroll
        for (int o = 16; o; o >>= 1) {
            mx0 = fmaxf(mx0, __shfl_xor_sync(0xffffffffu, mx0, o));
            mx1 = fmaxf(mx1, __shfl_xor_sync(0xffffffffu, mx1, o));
        }
        float sum0 = 0.f, sum1 = 0.f;
        float* p0 = sprb + (w * 2) * NQ;
        float* p1 = p0 + NQ;
        cnt = 0;
        for (int kk = lane; kk < NQ; kk += 32) {
            float e0 = __expf(s0[cnt] - mx0);
            float e1 = __expf(s1[cnt] - mx1);
            p0[kk] = e0; p1[kk] = e1;
            sum0 += e0; sum1 += e1;
            cnt++;
        }
#pragma unroll
        for (int o = 16; o; o >>= 1) {
            sum0 += __shfl_xor_sync(0xffffffffu, sum0, o);
            sum1 += __shfl_xor_sync(0xffffffffu, sum1, o);
        }
        float inv0 = 1.f / sum0, inv1 = 1.f / sum1;
        __syncwarp();

        // AV: lane owns output dim = lane, both rows share the v load
        float acc0 = 0.f, acc1 = 0.f;
#pragma unroll 4
        for (int kk = 0; kk < NQ; kk++) {
            float v = sv[kk * KPAD + lane];
            acc0 += p0[kk] * v;
            acc1 += p1[kk] * v;
        }
        g_att[((size_t)b * NQ + r0) * CDIM + h * HD + lane] = acc0 * inv0;
        g_att[((size_t)b * NQ + r1) * CDIM + h * HD + lane] = acc1 * inv1;
        __syncwarp();   // protect sprb before next pair
    }
}

// ============================================================
// Kernel 4: output projection  g_att @ wproj + bproj -> out
// ============================================================
__global__ __launch_bounds__(256) void proj_gemm_kernel(
    const float* __restrict__ wproj,
    const float* __restrict__ bproj,
    float* __restrict__ out)
{
    __shared__ float As[BK][BM];
    __shared__ float Bs[BK][BN];

    const int m0 = blockIdx.x * BM;
    const int j0 = blockIdx.y * BN;
    const int tid = threadIdx.x;
    const int ty = tid >> 4;
    const int tx = tid & 15;

    float acc[8][4];
#pragma unroll
    for (int i = 0; i < 8; i++)
#pragma unroll
        for (int j = 0; j < 4; j++) acc[i][j] = 0.f;

    for (int k0 = 0; k0 < CDIM; k0 += BK) {
#pragma unroll
        for (int p = tid; p < (BM * BK) / 4; p += 256) {
            int row = p >> 2, kq = p & 3;
            float4 v = *(const float4*)&g_att[(size_t)(m0 + row) * CDIM + k0 + kq * 4];
            As[kq * 4 + 0][row] = v.x;
            As[kq * 4 + 1][row] = v.y;
            As[kq * 4 + 2][row] = v.z;
            As[kq * 4 + 3][row] = v.w;
        }
        {
            int kk = tid >> 4, j4 = tid & 15;
            float4 v = *(const float4*)&wproj[(size_t)(k0 + kk) * CDIM + j0 + j4 * 4];
            *(float4*)&Bs[kk][j4 * 4] = v;
        }
        __syncthreads();
#pragma unroll
        for (int kk = 0; kk < BK; kk++) {
            float4 a0 = *(const float4*)&As[kk][ty * 8];
            float4 a1 = *(const float4*)&As[kk][ty * 8 + 4];
            float4 bv = *(const float4*)&Bs[kk][tx * 4];
            float a[8] = {a0.x, a0.y, a0.z, a0.w, a1.x, a1.y, a1.z, a1.w};
            float bb[4] = {bv.x, bv.y, bv.z, bv.w};
#pragma unroll
            for (int i = 0; i < 8; i++)
#pragma unroll
                for (int j = 0; j < 4; j++) acc[i][j] += a[i] * bb[j];
        }
        __syncthreads();
    }
    float4 bias = *(const float4*)&bproj[j0 + tx * 4];
#pragma unroll
    for (int i = 0; i < 8; i++) {
        float4 o = make_float4(acc[i][0] + bias.x, acc[i][1] + bias.y,
                               acc[i][2] + bias.z, acc[i][3] + bias.w);
        *(float4*)&out[(size_t)(m0 + ty * 8 + i) * CDIM + j0 + tx * 4] = o;
    }
}

// ============================================================
// launch
// ============================================================
extern "C" void kernel_launch(void* const* d_in, const int* in_sizes, int n_in,
                              void* d_out, int out_size)
{
    const float* x     = (const float*)d_in[0];
    const float* wq    = (const float*)d_in[1];
    const float* wkv   = (const float*)d_in[2];
    const float* wproj = (const float*)d_in[3];
    const float* bproj = (const float*)d_in[4];
    const float* pp_w  = (const float*)d_in[5];
    const float* pp_b  = (const float*)d_in[6];
    const float* ln1_g = (const float*)d_in[7];
    const float* ln1_b = (const float*)d_in[8];
    const float* l1_w  = (const float*)d_in[9];
    const float* l1_b  = (const float*)d_in[10];
    const float* ln2_g = (const float*)d_in[11];
    const float* ln2_b = (const float*)d_in[12];
    const float* l2_w  = (const float*)d_in[13];
    const float* l2_b  = (const float*)d_in[14];
    const float* ln3_g = (const float*)d_in[15];
    const float* ln3_b = (const float*)d_in[16];
    const float* l3_w  = (const float*)d_in[17];
    const float* l3_b  = (const float*)d_in[18];
    float* out = (float*)d_out;

    cudaFuncSetAttribute(attn_kernel,
                         cudaFuncAttributeMaxDynamicSharedMemorySize,
                         SMEM_ATTN_BYTES);

    pos_mlp_kernel<<<3, 256>>>(pp_w, pp_b, ln1_g, ln1_b, l1_w, l1_b,
                               ln2_g, ln2_b, l2_w, l2_b,
                               ln3_g, ln3_b, l3_w, l3_b);

    qkv_gemm_kernel<<<dim3(MTOT / BM, KVN / BN), 256>>>(x, wq, wkv);

    attn_kernel<<<dim3(BATCH, NH), 256, SMEM_ATTN_BYTES>>>();

    proj_gemm_kernel<<<dim3(MTOT / BM, CDIM / BN), 256>>>(wproj, bproj, out);
}

// round 2
// speedup vs baseline: 1.0003x; 1.0003x over previous
#include <cuda_runtime.h>
#include <math.h>

#define GS    14
#define NQ    196            // GS*GS
#define CDIM  128
#define NH    4
#define HD    32
#define BATCH 1024
#define MTOT  (BATCH * NQ)   // 200704
#define KVN   384            // q(128) | k(128) | v(128)
#define TAB   729            // (2*GS-1)^2
#define SCALE 0.17677669529663688f   // 32^-0.5

// ---- scratch (static device allocations; no cudaMalloc allowed) ----
__device__ float g_qkv[(size_t)MTOT * KVN];   // ~308 MB
__device__ float g_att[(size_t)MTOT * CDIM];  // ~103 MB
__device__ float g_pos[TAB * NH];             // pos-bias MLP table

// ============================================================
// Kernel 1: dynamic position-bias MLP (729 rows, tiny)
// ============================================================
__device__ __forceinline__ void ln_relu8(float* x, const float* g, const float* b) {
    float mu = 0.f;
#pragma unroll
    for (int d = 0; d < 8; d++) mu += x[d];
    mu *= 0.125f;
    float var = 0.f;
#pragma unroll
    for (int d = 0; d < 8; d++) { float t = x[d] - mu; var += t * t; }
    var *= 0.125f;
    float inv = rsqrtf(var + 1e-5f);
#pragma unroll
    for (int d = 0; d < 8; d++) {
        float t = (x[d] - mu) * inv * g[d] + b[d];
        x[d] = t > 0.f ? t : 0.f;
    }
}

__global__ void pos_mlp_kernel(
    const float* __restrict__ pp_w, const float* __restrict__ pp_b,
    const float* __restrict__ ln1_g, const float* __restrict__ ln1_b,
    const float* __restrict__ l1_w,  const float* __restrict__ l1_b,
    const float* __restrict__ ln2_g, const float* __restrict__ ln2_b,
    const float* __restrict__ l2_w,  const float* __restrict__ l2_b,
    const float* __restrict__ ln3_g, const float* __restrict__ ln3_b,
    const float* __restrict__ l3_w,  const float* __restrict__ l3_b)
{
    int m = blockIdx.x * blockDim.x + threadIdx.x;
    if (m >= TAB) return;
    float bi = (float)(m / 27 - 13);
    float bj = (float)(m % 27 - 13);
    float h[8], t[8];
#pragma unroll
    for (int d = 0; d < 8; d++) h[d] = bi * pp_w[d] + bj * pp_w[8 + d] + pp_b[d];
    ln_relu8(h, ln1_g, ln1_b);
#pragma unroll
    for (int j = 0; j < 8; j++) {
        float a = l1_b[j];
#pragma unroll
        for (int d = 0; d < 8; d++) a += h[d] * l1_w[d * 8 + j];
        t[j] = a;
    }
    ln_relu8(t, ln2_g, ln2_b);
#pragma unroll
    for (int j = 0; j < 8; j++) {
        float a = l2_b[j];
#pragma unroll
        for (int d = 0; d < 8; d++) a += t[d] * l2_w[d * 8 + j];
        h[j] = a;
    }
    ln_relu8(h, ln3_g, ln3_b);
#pragma unroll
    for (int j = 0; j < NH; j++) {
        float a = l3_b[j];
#pragma unroll
        for (int d = 0; d < 8; d++) a += h[d] * l3_w[d * NH + j];
        g_pos[m * NH + j] = a;
    }
}

// ============================================================
// Kernel 2: fused QKV GEMM  [200704,128] x [128,384] -> g_qkv
//   cols 0..127  = x @ wq
//   cols 128..383 = x @ wkv   (k = 128..255, v = 256..383)
// ============================================================
#define BM 128
#define BN 64
#define BK 16

__global__ __launch_bounds__(256) void qkv_gemm_kernel(
    const float* __restrict__ x,
    const float* __restrict__ wq,
    const float* __restrict__ wkv)
{
    __shared__ float As[BK][BM];
    __shared__ float Bs[BK][BN];

    const int m0 = blockIdx.x * BM;
    const int j0 = blockIdx.y * BN;
    const int tid = threadIdx.x;
    const int ty = tid >> 4;     // 0..15 -> 8 rows each
    const int tx = tid & 15;     // 0..15 -> 4 cols each

    const float* wsrc; int ldw, c0;
    if (j0 < 128) { wsrc = wq;  ldw = 128; c0 = j0; }
    else          { wsrc = wkv; ldw = 256; c0 = j0 - 128; }

    float acc[8][4];
#pragma unroll
    for (int i = 0; i < 8; i++)
#pragma unroll
        for (int j = 0; j < 4; j++) acc[i][j] = 0.f;

    for (int k0 = 0; k0 < CDIM; k0 += BK) {
        // load A tile (transposed into As[k][m]); 512 float4 total, 2 per thread
#pragma unroll
        for (int p = tid; p < (BM * BK) / 4; p += 256) {
            int row = p >> 2, kq = p & 3;
            float4 v = *(const float4*)&x[(size_t)(m0 + row) * CDIM + k0 + kq * 4];
            As[kq * 4 + 0][row] = v.x;
            As[kq * 4 + 1][row] = v.y;
            As[kq * 4 + 2][row] = v.z;
            As[kq * 4 + 3][row] = v.w;
        }
        // load B tile; 256 float4 total, 1 per thread
        {
            int kk = tid >> 4, j4 = tid & 15;
            float4 v = *(const float4*)&wsrc[(size_t)(k0 + kk) * ldw + c0 + j4 * 4];
            *(float4*)&Bs[kk][j4 * 4] = v;
        }
        __syncthreads();
#pragma unroll
        for (int kk = 0; kk < BK; kk++) {
            float4 a0 = *(const float4*)&As[kk][ty * 8];
            float4 a1 = *(const float4*)&As[kk][ty * 8 + 4];
            float4 bv = *(const float4*)&Bs[kk][tx * 4];
            float a[8] = {a0.x, a0.y, a0.z, a0.w, a1.x, a1.y, a1.z, a1.w};
            float bb[4] = {bv.x, bv.y, bv.z, bv.w};
#pragma unroll
            for (int i = 0; i < 8; i++)
#pragma unroll
                for (int j = 0; j < 4; j++) acc[i][j] += a[i] * bb[j];
        }
        __syncthreads();
    }
#pragma unroll
    for (int i = 0; i < 8; i++) {
        float4 o = make_float4(acc[i][0], acc[i][1], acc[i][2], acc[i][3]);
        *(float4*)&g_qkv[(size_t)(m0 + ty * 8 + i) * KVN + j0 + tx * 4] = o;
    }
}

// ============================================================
// Kernel 3: attention per (batch, head) CTA
//   scores = qk^T*scale + bias -> softmax -> @ v  -> g_att
// ============================================================
#define KPAD 33   // 32+1 pad: conflict-free for both row-dot and dim-per-lane access
#define SM_Q   0
#define SM_K   (NQ * KPAD)
#define SM_V   (2 * NQ * KPAD)
#define SM_POS (3 * NQ * KPAD)
#define SM_PRB (3 * NQ * KPAD + TAB * NH)
#define SMEM_ATTN_FLOATS (3 * NQ * KPAD + TAB * NH + 16 * NQ)
#define SMEM_ATTN_BYTES  (SMEM_ATTN_FLOATS * 4)

__global__ __launch_bounds__(256, 2) void attn_kernel()
{
    extern __shared__ float sm[];
    float* sq   = sm + SM_Q;
    float* sk   = sm + SM_K;
    float* sv   = sm + SM_V;
    float* spos = sm + SM_POS;
    float* sprb = sm + SM_PRB;

    const int b = blockIdx.x;
    const int h = blockIdx.y;
    const int tid = threadIdx.x;

    // stage q/k/v for this (b,h) + the pos table
    const float* base = g_qkv + (size_t)b * NQ * KVN + h * HD;
    for (int idx = tid; idx < NQ * HD; idx += 256) {
        int n = idx >> 5, d = idx & 31;
        const float* row = base + (size_t)n * KVN;
        sq[n * KPAD + d] = row[d];
        sk[n * KPAD + d] = row[128 + d];
        sv[n * KPAD + d] = row[256 + d];
    }
    for (int idx = tid; idx < TAB * NH; idx += 256) spos[idx] = g_pos[idx];
    __syncthreads();

    const int w = tid >> 5, lane = tid & 31;

    // each warp handles query-row pairs (r0, r0+1); TQ=2 halves smem traffic
    for (int r0 = w * 2; r0 < NQ; r0 += 16) {
        const int r1 = r0 + 1;
        const int qi0 = r0 / GS, qj0 = r0 - qi0 * GS;
        const int qi1 = r1 / GS, qj1 = r1 - qi1 * GS;

        float q0[HD], q1[HD];
#pragma unroll
        for (int d = 0; d < HD; d++) {
            q0[d] = sq[r0 * KPAD + d];
            q1[d] = sq[r1 * KPAD + d];
        }

        float s0[7], s1[7];
        float mx0 = -1e30f, mx1 = -1e30f;
        int cnt = 0;
        for (int kk = lane; kk < NQ; kk += 32) {
            const float* kr = sk + kk * KPAD;
            float a = 0.f, c = 0.f;
#pragma unroll
            for (int d = 0; d < HD; d++) {
                float kv = kr[d];
                a += q0[d] * kv;
                c += q1[d] * kv;
            }
            int ki = kk / GS, kj = kk - ki * GS;
            int pbase0 = ((qi0 - ki + GS - 1) * (2 * GS - 1) + (qj0 - kj + GS - 1)) * NH + h;
            int pbase1 = ((qi1 - ki + GS - 1) * (2 * GS - 1) + (qj1 - kj + GS - 1)) * NH + h;
            a = a * SCALE + spos[pbase0];
            c = c * SCALE + spos[pbase1];
            s0[cnt] = a; s1[cnt] = c; cnt++;
            mx0 = fmaxf(mx0, a);
            mx1 = fmaxf(mx1, c);
        }
#pragma unroll
        for (int o = 16; o; o >>= 1) {
            mx0 = fmaxf(mx0, __shfl_xor_sync(0xffffffffu, mx0, o));
            mx1 = fmaxf(mx1, __shfl_xor_sync(0xffffffffu, mx1, o));
        }
        float sum0 = 0.f, sum1 = 0.f;
        float* p0 = sprb + (w * 2) * NQ;
        float* p1 = p0 + NQ;
        cnt = 0;
        for (int kk = lane; kk < NQ; kk += 32) {
            float e0 = __expf(s0[cnt] - mx0);
            float e1 = __expf(s1[cnt] - mx1);
            p0[kk] = e0; p1[kk] = e1;
            sum0 += e0; sum1 += e1;
            cnt++;
        }
#pragma unroll
        for (int o = 16; o; o >>= 1) {
            sum0 += __shfl_xor_sync(0xffffffffu, sum0, o);
            sum1 += __shfl_xor_sync(0xffffffffu, sum1, o);
        }
        float inv0 = 1.f / sum0, inv1 = 1.f / sum1;
        __syncwarp();

        // AV: lane owns output dim = lane, both rows share the v load
        float acc0 = 0.f, acc1 = 0.f;
#pragma unroll 4
        for (int kk = 0; kk < NQ; kk++) {
            float v = sv[kk * KPAD + lane];
            acc0 += p0[kk] * v;
            acc1 += p1[kk] * v;
        }
        g_att[((size_t)b * NQ + r0) * CDIM + h * HD + lane] = acc0 * inv0;
        g_att[((size_t)b * NQ + r1) * CDIM + h * HD + lane] = acc1 * inv1;
        __syncwarp();   // protect sprb before next pair
    }
}

// ============================================================
// Kernel 4: output projection  g_att @ wproj + bproj -> out
// ============================================================
__global__ __launch_bounds__(256) void proj_gemm_kernel(
    const float* __restrict__ wproj,
    const float* __restrict__ bproj,
    float* __restrict__ out)
{
    __shared__ float As[BK][BM];
    __shared__ float Bs[BK][BN];

    const int m0 = blockIdx.x * BM;
    const int j0 = blockIdx.y * BN;
    const int tid = threadIdx.x;
    const int ty = tid >> 4;
    const int tx = tid & 15;

    float acc[8][4];
#pragma unroll
    for (int i = 0; i < 8; i++)
#pragma unroll
        for (int j = 0; j < 4; j++) acc[i][j] = 0.f;

    for (int k0 = 0; k0 < CDIM; k0 += BK) {
#pragma unroll
        for (int p = tid; p < (BM * BK) / 4; p += 256) {
            int row = p >> 2, kq = p & 3;
            float4 v = *(const float4*)&g_att[(size_t)(m0 + row) * CDIM + k0 + kq * 4];
            As[kq * 4 + 0][row] = v.x;
            As[kq * 4 + 1][row] = v.y;
            As[kq * 4 + 2][row] = v.z;
            As[kq * 4 + 3][row] = v.w;
        }
        {
            int kk = tid >> 4, j4 = tid & 15;
            float4 v = *(const float4*)&wproj[(size_t)(k0 + kk) * CDIM + j0 + j4 * 4];
            *(float4*)&Bs[kk][j4 * 4] = v;
        }
        __syncthreads();
#pragma unroll
        for (int kk = 0; kk < BK; kk++) {
            float4 a0 = *(const float4*)&As[kk][ty * 8];
            float4 a1 = *(const float4*)&As[kk][ty * 8 + 4];
            float4 bv = *(const float4*)&Bs[kk][tx * 4];
            float a[8] = {a0.x, a0.y, a0.z, a0.w, a1.x, a1.y, a1.z, a1.w};
            float bb[4] = {bv.x, bv.y, bv.z, bv.w};
#pragma unroll
            for (int i = 0; i < 8; i++)
#pragma unroll
                for (int j = 0; j < 4; j++) acc[i][j] += a[i] * bb[j];
        }
        __syncthreads();
    }
    float4 bias = *(const float4*)&bproj[j0 + tx * 4];
#pragma unroll
    for (int i = 0; i < 8; i++) {
        float4 o = make_float4(acc[i][0] + bias.x, acc[i][1] + bias.y,
                               acc[i][2] + bias.z, acc[i][3] + bias.w);
        *(float4*)&out[(size_t)(m0 + ty * 8 + i) * CDIM + j0 + tx * 4] = o;
    }
}

// ============================================================
// launch
// ============================================================
extern "C" void kernel_launch(void* const* d_in, const int* in_sizes, int n_in,
                              void* d_out, int out_size)
{
    const float* x     = (const float*)d_in[0];
    const float* wq    = (const float*)d_in[1];
    const float* wkv   = (const float*)d_in[2];
    const float* wproj = (const float*)d_in[3];
    const float* bproj = (const float*)d_in[4];
    const float* pp_w  = (const float*)d_in[5];
    const float* pp_b  = (const float*)d_in[6];
    const float* ln1_g = (const float*)d_in[7];
    const float* ln1_b = (const float*)d_in[8];
    const float* l1_w  = (const float*)d_in[9];
    const float* l1_b  = (const float*)d_in[10];
    const float* ln2_g = (const float*)d_in[11];
    const float* ln2_b = (const float*)d_in[12];
    const float* l2_w  = (const float*)d_in[13];
    const float* l2_b  = (const float*)d_in[14];
    const float* ln3_g = (const float*)d_in[15];
    const float* ln3_b = (const float*)d_in[16];
    const float* l3_w  = (const float*)d_in[17];
    const float* l3_b  = (const float*)d_in[18];
    float* out = (float*)d_out;

    cudaFuncSetAttribute(attn_kernel,
                         cudaFuncAttributeMaxDynamicSharedMemorySize,
                         SMEM_ATTN_BYTES);

    pos_mlp_kernel<<<3, 256>>>(pp_w, pp_b, ln1_g, ln1_b, l1_w, l1_b,
                               ln2_g, ln2_b, l2_w, l2_b,
                               ln3_g, ln3_b, l3_w, l3_b);

    qkv_gemm_kernel<<<dim3(MTOT / BM, KVN / BN), 256>>>(x, wq, wkv);

    attn_kernel<<<dim3(BATCH, NH), 256, SMEM_ATTN_BYTES>>>();

    proj_gemm_kernel<<<dim3(MTOT / BM, CDIM / BN), 256>>>(wproj, bproj, out);
}

// round 4
// speedup vs baseline: 1.1588x; 1.1585x over previous
#include <cuda_runtime.h>
#include <cuda_bf16.h>
#include <math.h>
#include <stdint.h>

#define GS    14
#define NQ    196            // GS*GS
#define CDIM  128
#define NH    4
#define HD    32
#define BATCH 1024
#define MTOT  (BATCH * NQ)   // 200704
#define KVN   384            // q(128) | k(128) | v(128)
#define TAB   729            // (2*GS-1)^2
#define SCALE 0.17677669529663688f   // 32^-0.5

// ---- scratch (static device allocations; no cudaMalloc allowed) ----
__device__ float g_qkv[(size_t)MTOT * KVN];   // ~308 MB
__device__ float g_att[(size_t)MTOT * CDIM];  // ~103 MB
__device__ float g_pos[TAB * NH];
__device__ __nv_bfloat16 g_wqkv_h[KVN * CDIM];   // [n=384][k=128]
__device__ __nv_bfloat16 g_wqkv_l[KVN * CDIM];
__device__ __nv_bfloat16 g_wp_h[CDIM * CDIM];    // [n=128][k=128]
__device__ __nv_bfloat16 g_wp_l[CDIM * CDIM];

// ============================================================
// helpers
// ============================================================
__device__ __forceinline__ uint32_t smem_u32(const void* p) {
    uint32_t a;
    asm("{ .reg .u64 t; cvta.to.shared.u64 t, %1; cvt.u32.u64 %0, t; }"
        : "=r"(a) : "l"(p));
    return a;
}
__device__ __forceinline__ void ldsm_x4(uint32_t& r0, uint32_t& r1,
                                        uint32_t& r2, uint32_t& r3, uint32_t addr) {
    asm volatile("ldmatrix.sync.aligned.m8n8.x4.shared.b16 {%0,%1,%2,%3}, [%4];"
                 : "=r"(r0), "=r"(r1), "=r"(r2), "=r"(r3) : "r"(addr));
}
__device__ __forceinline__ void mma16816(float* d, const uint32_t* a, const uint32_t* b) {
    asm volatile("mma.sync.aligned.m16n8k16.row.col.f32.bf16.bf16.f32 "
                 "{%0,%1,%2,%3}, {%4,%5,%6,%7}, {%8,%9}, {%0,%1,%2,%3};"
                 : "+f"(d[0]), "+f"(d[1]), "+f"(d[2]), "+f"(d[3])
                 : "r"(a[0]), "r"(a[1]), "r"(a[2]), "r"(a[3]),
                   "r"(b[0]), "r"(b[1]));
}
// swizzled byte offset inside a 128x128 bf16 tile (256B rows, 16B chunks)
__device__ __forceinline__ uint32_t swz(int row, int chunk) {
    return (uint32_t)(row * 256 + ((chunk ^ (row & 7)) << 4));
}

// ============================================================
// Kernel 1: dynamic position-bias MLP (729 rows, tiny)
// ============================================================
__device__ __forceinline__ void ln_relu8(float* x, const float* g, const float* b) {
    float mu = 0.f;
#pragma unroll
    for (int d = 0; d < 8; d++) mu += x[d];
    mu *= 0.125f;
    float var = 0.f;
#pragma unroll
    for (int d = 0; d < 8; d++) { float t = x[d] - mu; var += t * t; }
    var *= 0.125f;
    float inv = rsqrtf(var + 1e-5f);
#pragma unroll
    for (int d = 0; d < 8; d++) {
        float t = (x[d] - mu) * inv * g[d] + b[d];
        x[d] = t > 0.f ? t : 0.f;
    }
}

__global__ void pos_mlp_kernel(
    const float* __restrict__ pp_w, const float* __restrict__ pp_b,
    const float* __restrict__ ln1_g, const float* __restrict__ ln1_b,
    const float* __restrict__ l1_w,  const float* __restrict__ l1_b,
    const float* __restrict__ ln2_g, const float* __restrict__ ln2_b,
    const float* __restrict__ l2_w,  const float* __restrict__ l2_b,
    const float* __restrict__ ln3_g, const float* __restrict__ ln3_b,
    const float* __restrict__ l3_w,  const float* __restrict__ l3_b)
{
    int m = blockIdx.x * blockDim.x + threadIdx.x;
    if (m >= TAB) return;
    float bi = (float)(m / 27 - 13);
    float bj = (float)(m % 27 - 13);
    float h[8], t[8];
#pragma unroll
    for (int d = 0; d < 8; d++) h[d] = bi * pp_w[d] + bj * pp_w[8 + d] + pp_b[d];
    ln_relu8(h, ln1_g, ln1_b);
#pragma unroll
    for (int j = 0; j < 8; j++) {
        float a = l1_b[j];
#pragma unroll
        for (int d = 0; d < 8; d++) a += h[d] * l1_w[d * 8 + j];
        t[j] = a;
    }
    ln_relu8(t, ln2_g, ln2_b);
#pragma unroll
    for (int j = 0; j < 8; j++) {
        float a = l2_b[j];
#pragma unroll
        for (int d = 0; d < 8; d++) a += t[d] * l2_w[d * 8 + j];
        h[j] = a;
    }
    ln_relu8(h, ln3_g, ln3_b);
#pragma unroll
    for (int j = 0; j < NH; j++) {
        float a = l3_b[j];
#pragma unroll
        for (int d = 0; d < 8; d++) a += h[d] * l3_w[d * NH + j];
        g_pos[m * NH + j] = a;
    }
}

// ============================================================
// Kernel: weight prep — transpose to [n][k], bf16 hi/lo split
// ============================================================
__global__ __launch_bounds__(256) void wprep_kernel(
    const float* __restrict__ wq, const float* __restrict__ wkv,
    const float* __restrict__ wproj)
{
    int idx = blockIdx.x * 256 + threadIdx.x;   // 384*128 + 128*128 = 65536
    if (idx < KVN * CDIM) {
        int n = idx >> 7, k = idx & 127;
        float v = (n < 128) ? wq[k * 128 + n] : wkv[k * 256 + (n - 128)];
        __nv_bfloat16 h = __float2bfloat16(v);
        g_wqkv_h[idx] = h;
        g_wqkv_l[idx] = __float2bfloat16(v - __bfloat162float(h));
    } else if (idx < KVN * CDIM + CDIM * CDIM) {
        int j = idx - KVN * CDIM;
        int n = j >> 7, k = j & 127;
        float v = wproj[k * 128 + n];
        __nv_bfloat16 h = __float2bfloat16(v);
        g_wp_h[j] = h;
        g_wp_l[j] = __float2bfloat16(v - __bfloat162float(h));
    }
}

// ============================================================
// Kernel: HMMA (mma.sync bf16) GEMM with fused fp32->hi/lo split
//   C[m0:m0+128, :] = A(fp32) @ B^T (+bias)
//   B given as bf16 hi/lo, [Ntot][128] k-major
//   D = Ah*Bh + Al*Bh + Ah*Bl  (fp32 accumulate)
//   mode 0: A = Ain (x),   C = g_qkv, NB=3, ldc=384, no bias
//   mode 1: A = g_att,     C = Cout,  NB=1, ldc=128, bias
// ============================================================
#define TILEB 32768
#define SM_AH 0
#define SM_AL TILEB
#define SM_BH (2 * TILEB)
#define SM_BL (3 * TILEB)
#define GSMEM (4 * TILEB)

__global__ __launch_bounds__(256) void hmma_gemm_kernel(
    int mode, const float* __restrict__ Ain,
    float* __restrict__ Cout, const float* __restrict__ bias)
{
    extern __shared__ char smc[];
    const uint32_t sb = smem_u32(smc);
    const int tid = threadIdx.x;
    const int w = tid >> 5, lane = tid & 31;
    const int m0 = blockIdx.x * 128;

    const float* A = (mode == 0) ? Ain : g_att;
    float* C = (mode == 0) ? g_qkv : Cout;
    const __nv_bfloat16* Bh = (mode == 0) ? g_wqkv_h : g_wp_h;
    const __nv_bfloat16* Bl = (mode == 0) ? g_wqkv_l : g_wp_l;
    const int NB  = (mode == 0) ? 3 : 1;
    const int ldc = (mode == 0) ? KVN : CDIM;
    const bool has_bias = (mode == 1);

    // ---- stage A: fp32 -> bf16 hi/lo, swizzled smem ----
    for (int idx = tid; idx < 2048; idx += 256) {
        int row = idx >> 4, c = idx & 15;
        const float* src = A + (size_t)(m0 + row) * CDIM + c * 8;
        float4 v0 = *(const float4*)src;
        float4 v1 = *(const float4*)(src + 4);
        float f[8] = {v0.x, v0.y, v0.z, v0.w, v1.x, v1.y, v1.z, v1.w};
        uint32_t hp[4], lp[4];
#pragma unroll
        for (int q = 0; q < 4; q++) {
            __nv_bfloat16 h0 = __float2bfloat16(f[2 * q]);
            __nv_bfloat16 h1 = __float2bfloat16(f[2 * q + 1]);
            __nv_bfloat162 hh = __halves2bfloat162(h0, h1);
            __nv_bfloat162 ll = __halves2bfloat162(
                __float2bfloat16(f[2 * q] - __bfloat162float(h0)),
                __float2bfloat16(f[2 * q + 1] - __bfloat162float(h1)));
            hp[q] = *(uint32_t*)&hh;
            lp[q] = *(uint32_t*)&ll;
        }
        uint32_t off = swz(row, c);
        *(uint4*)(smc + SM_AH + off) = make_uint4(hp[0], hp[1], hp[2], hp[3]);
        *(uint4*)(smc + SM_AL + off) = make_uint4(lp[0], lp[1], lp[2], lp[3]);
    }

    const int wm = w >> 1;        // 0..3 -> m32
    const int wn = w & 1;         // 0..1 -> n64
    const int lrow = lane & 15;
    const int lchunk = lane >> 4;

    for (int nb = 0; nb < NB; nb++) {
        const int n0 = nb * 128;
        __syncthreads();   // prior nb's reads done (and A staged on first iter)

        // ---- stage B tile (bf16 hi/lo, already [n][k]) ----
        for (int idx = tid; idx < 2048; idx += 256) {
            int row = idx >> 4, c = idx & 15;
            size_t gi = (size_t)(n0 + row) * CDIM + c * 8;
            uint4 vh = *(const uint4*)(Bh + gi);
            uint4 vl = *(const uint4*)(Bl + gi);
            uint32_t off = swz(row, c);
            *(uint4*)(smc + SM_BH + off) = vh;
            *(uint4*)(smc + SM_BL + off) = vl;
        }
        __syncthreads();

        float d[2][8][4];
#pragma unroll
        for (int mi = 0; mi < 2; mi++)
#pragma unroll
            for (int ni = 0; ni < 8; ni++)
#pragma unroll
                for (int q = 0; q < 4; q++) d[mi][ni][q] = 0.f;

#pragma unroll 1
        for (int term = 0; term < 3; term++) {
            const uint32_t aBase = sb + ((term == 1) ? SM_AL : SM_AH);
            const uint32_t bBase = sb + ((term == 2) ? SM_BL : SM_BH);
#pragma unroll
            for (int ks = 0; ks < 8; ks++) {
                const int chunk = ks * 2 + lchunk;
                uint32_t a[2][4];
#pragma unroll
                for (int mi = 0; mi < 2; mi++) {
                    int row = wm * 32 + mi * 16 + lrow;
                    ldsm_x4(a[mi][0], a[mi][1], a[mi][2], a[mi][3],
                            aBase + swz(row, chunk));
                }
                uint32_t b[8][2];
#pragma unroll
                for (int np = 0; np < 4; np++) {
                    int row = wn * 64 + np * 16 + lrow;
                    uint32_t r0, r1, r2, r3;
                    ldsm_x4(r0, r1, r2, r3, bBase + swz(row, chunk));
                    b[2 * np][0] = r0; b[2 * np + 1][0] = r1;
                    b[2 * np][1] = r2; b[2 * np + 1][1] = r3;
                }
#pragma unroll
                for (int mi = 0; mi < 2; mi++)
#pragma unroll
                    for (int ni = 0; ni < 8; ni++)
                        mma16816(d[mi][ni], a[mi], b[ni]);
            }
        }

        // ---- epilogue ----
        const int mrow = m0 + wm * 32 + (lane >> 2);
        const int ncol = n0 + wn * 64 + (lane & 3) * 2;
#pragma unroll
        for (int mi = 0; mi < 2; mi++) {
#pragma unroll
            for (int ni = 0; ni < 8; ni++) {
                float b0 = 0.f, b1 = 0.f;
                if (has_bias) {
                    b0 = bias[ncol + ni * 8];
                    b1 = bias[ncol + ni * 8 + 1];
                }
                float* p0 = C + (size_t)(mrow + mi * 16) * ldc + ncol + ni * 8;
                float* p1 = C + (size_t)(mrow + mi * 16 + 8) * ldc + ncol + ni * 8;
                *(float2*)p0 = make_float2(d[mi][ni][0] + b0, d[mi][ni][1] + b1);
                *(float2*)p1 = make_float2(d[mi][ni][2] + b0, d[mi][ni][3] + b1);
            }
        }
    }
}

// ============================================================
// Kernel: attention per (batch, head) CTA (unchanged — passed R2)
// ============================================================
#define KPAD 33
#define SM_Q   0
#define SM_K   (NQ * KPAD)
#define SM_V   (2 * NQ * KPAD)
#define SM_POS (3 * NQ * KPAD)
#define SM_PRB (3 * NQ * KPAD + TAB * NH)
#define SMEM_ATTN_FLOATS (3 * NQ * KPAD + TAB * NH + 16 * NQ)
#define SMEM_ATTN_BYTES  (SMEM_ATTN_FLOATS * 4)

__global__ __launch_bounds__(256, 2) void attn_kernel()
{
    extern __shared__ float smf[];
    float* sq   = smf + SM_Q;
    float* sk   = smf + SM_K;
    float* sv   = smf + SM_V;
    float* spos = smf + SM_POS;
    float* sprb = smf + SM_PRB;

    const int b = blockIdx.x;
    const int h = blockIdx.y;
    const int tid = threadIdx.x;

    const float* base = g_qkv + (size_t)b * NQ * KVN + h * HD;
    for (int idx = tid; idx < NQ * HD; idx += 256) {
        int n = idx >> 5, d = idx & 31;
        const float* row = base + (size_t)n * KVN;
        sq[n * KPAD + d] = row[d];
        sk[n * KPAD + d] = row[128 + d];
        sv[n * KPAD + d] = row[256 + d];
    }
    for (int idx = tid; idx < TAB * NH; idx += 256) spos[idx] = g_pos[idx];
    __syncthreads();

    const int w = tid >> 5, lane = tid & 31;

    for (int r0 = w * 2; r0 < NQ; r0 += 16) {
        const int r1 = r0 + 1;
        const int qi0 = r0 / GS, qj0 = r0 - qi0 * GS;
        const int qi1 = r1 / GS, qj1 = r1 - qi1 * GS;

        float q0[HD], q1[HD];
#pragma unroll
        for (int d = 0; d < HD; d++) {
            q0[d] = sq[r0 * KPAD + d];
            q1[d] = sq[r1 * KPAD + d];
        }

        float s0[7], s1[7];
        float mx0 = -1e30f, mx1 = -1e30f;
        int cnt = 0;
        for (int kk = lane; kk < NQ; kk += 32) {
            const float* kr = sk + kk * KPAD;
            float a = 0.f, c = 0.f;
#pragma unroll
            for (int d = 0; d < HD; d++) {
                float kv = kr[d];
                a += q0[d] * kv;
                c += q1[d] * kv;
            }
            int ki = kk / GS, kj = kk - ki * GS;
            int pbase0 = ((qi0 - ki + GS - 1) * (2 * GS - 1) + (qj0 - kj + GS - 1)) * NH + h;
            int pbase1 = ((qi1 - ki + GS - 1) * (2 * GS - 1) + (qj1 - kj + GS - 1)) * NH + h;
            a = a * SCALE + spos[pbase0];
            c = c * SCALE + spos[pbase1];
            s0[cnt] = a; s1[cnt] = c; cnt++;
            mx0 = fmaxf(mx0, a);
            mx1 = fmaxf(mx1, c);
        }
#pragma unroll
        for (int o = 16; o; o >>= 1) {
            mx0 = fmaxf(mx0, __shfl_xor_sync(0xffffffffu, mx0, o));
            mx1 = fmaxf(mx1, __shfl_xor_sync(0xffffffffu, mx1, o));
        }
        float sum0 = 0.f, sum1 = 0.f;
        float* p0 = sprb + (w * 2) * NQ;
        float* p1 = p0 + NQ;
        cnt = 0;
        for (int kk = lane; kk < NQ; kk += 32) {
            float e0 = __expf(s0[cnt] - mx0);
            float e1 = __expf(s1[cnt] - mx1);
            p0[kk] = e0; p1[kk] = e1;
            sum0 += e0; sum1 += e1;
            cnt++;
        }
#pragma unroll
        for (int o = 16; o; o >>= 1) {
            sum0 += __shfl_xor_sync(0xffffffffu, sum0, o);
            sum1 += __shfl_xor_sync(0xffffffffu, sum1, o);
        }
        float inv0 = 1.f / sum0, inv1 = 1.f / sum1;
        __syncwarp();

        float acc0 = 0.f, acc1 = 0.f;
#pragma unroll 4
        for (int kk = 0; kk < NQ; kk++) {
            float v = sv[kk * KPAD + lane];
            acc0 += p0[kk] * v;
            acc1 += p1[kk] * v;
        }
        g_att[((size_t)b * NQ + r0) * CDIM + h * HD + lane] = acc0 * inv0;
        g_att[((size_t)b * NQ + r1) * CDIM + h * HD + lane] = acc1 * inv1;
        __syncwarp();
    }
}

// ============================================================
// launch
// ============================================================
extern "C" void kernel_launch(void* const* d_in, const int* in_sizes, int n_in,
                              void* d_out, int out_size)
{
    const float* x     = (const float*)d_in[0];
    const float* wq    = (const float*)d_in[1];
    const float* wkv   = (const float*)d_in[2];
    const float* wproj = (const float*)d_in[3];
    const float* bproj = (const float*)d_in[4];
    const float* pp_w  = (const float*)d_in[5];
    const float* pp_b  = (const float*)d_in[6];
    const float* ln1_g = (const float*)d_in[7];
    const float* ln1_b = (const float*)d_in[8];
    const float* l1_w  = (const float*)d_in[9];
    const float* l1_b  = (const float*)d_in[10];
    const float* ln2_g = (const float*)d_in[11];
    const float* ln2_b = (const float*)d_in[12];
    const float* l2_w  = (const float*)d_in[13];
    const float* l2_b  = (const float*)d_in[14];
    const float* ln3_g = (const float*)d_in[15];
    const float* ln3_b = (const float*)d_in[16];
    const float* l3_w  = (const float*)d_in[17];
    const float* l3_b  = (const float*)d_in[18];
    float* out = (float*)d_out;

    cudaFuncSetAttribute(attn_kernel,
                         cudaFuncAttributeMaxDynamicSharedMemorySize,
                         SMEM_ATTN_BYTES);
    cudaFuncSetAttribute(hmma_gemm_kernel,
                         cudaFuncAttributeMaxDynamicSharedMemorySize,
                         GSMEM);

    pos_mlp_kernel<<<3, 256>>>(pp_w, pp_b, ln1_g, ln1_b, l1_w, l1_b,
                               ln2_g, ln2_b, l2_w, l2_b,
                               ln3_g, ln3_b, l3_w, l3_b);

    wprep_kernel<<<256, 256>>>(wq, wkv, wproj);

    // QKV: x @ [wq|wkv] -> g_qkv
    hmma_gemm_kernel<<<MTOT / 128, 256, GSMEM>>>(0, x, nullptr, nullptr);

    attn_kernel<<<dim3(BATCH, NH), 256, SMEM_ATTN_BYTES>>>();

    // Proj: g_att @ wproj + bproj -> out
    hmma_gemm_kernel<<<MTOT / 128, 256, GSMEM>>>(1, nullptr, out, bproj);
}

// round 5
// speedup vs baseline: 2.1181x; 1.8278x over previous
#include <cuda_runtime.h>
#include <cuda_bf16.h>
#include <math.h>
#include <stdint.h>

#define GS    14
#define NQ    196            // GS*GS
#define CDIM  128
#define NH    4
#define HD    32
#define BATCH 1024
#define MTOT  (BATCH * NQ)   // 200704
#define KVN   384            // q(128) | k(128) | v(128)
#define TAB   729            // (2*GS-1)^2
#define SCALE 0.17677669529663688f   // 32^-0.5

// ---- scratch (static device allocations; no cudaMalloc allowed) ----
__device__ float g_qkv[(size_t)MTOT * KVN];   // ~308 MB
__device__ float g_att[(size_t)MTOT * CDIM];  // ~103 MB
__device__ float g_pos[TAB * NH];
__device__ __nv_bfloat16 g_wqkv_h[KVN * CDIM];   // [n=384][k=128]
__device__ __nv_bfloat16 g_wqkv_l[KVN * CDIM];
__device__ __nv_bfloat16 g_wp_h[CDIM * CDIM];    // [n=128][k=128]
__device__ __nv_bfloat16 g_wp_l[CDIM * CDIM];

// ============================================================
// helpers
// ============================================================
__device__ __forceinline__ uint32_t smem_u32(const void* p) {
    uint32_t a;
    asm("{ .reg .u64 t; cvta.to.shared.u64 t, %1; cvt.u32.u64 %0, t; }"
        : "=r"(a) : "l"(p));
    return a;
}
__device__ __forceinline__ void ldsm_x4(uint32_t& r0, uint32_t& r1,
                                        uint32_t& r2, uint32_t& r3, uint32_t addr) {
    asm volatile("ldmatrix.sync.aligned.m8n8.x4.shared.b16 {%0,%1,%2,%3}, [%4];"
                 : "=r"(r0), "=r"(r1), "=r"(r2), "=r"(r3) : "r"(addr));
}
__device__ __forceinline__ void mma16816(float* d, const uint32_t* a, const uint32_t* b) {
    asm volatile("mma.sync.aligned.m16n8k16.row.col.f32.bf16.bf16.f32 "
                 "{%0,%1,%2,%3}, {%4,%5,%6,%7}, {%8,%9}, {%0,%1,%2,%3};"
                 : "+f"(d[0]), "+f"(d[1]), "+f"(d[2]), "+f"(d[3])
                 : "r"(a[0]), "r"(a[1]), "r"(a[2]), "r"(a[3]),
                   "r"(b[0]), "r"(b[1]));
}
// swizzled byte offset inside a 128x128 bf16 tile (256B rows, 16B chunks)
__device__ __forceinline__ uint32_t swz(int row, int chunk) {
    return (uint32_t)(row * 256 + ((chunk ^ (row & 7)) << 4));
}

// ============================================================
// Kernel 1: dynamic position-bias MLP (729 rows, tiny)
// ============================================================
__device__ __forceinline__ void ln_relu8(float* x, const float* g, const float* b) {
    float mu = 0.f;
#pragma unroll
    for (int d = 0; d < 8; d++) mu += x[d];
    mu *= 0.125f;
    float var = 0.f;
#pragma unroll
    for (int d = 0; d < 8; d++) { float t = x[d] - mu; var += t * t; }
    var *= 0.125f;
    float inv = rsqrtf(var + 1e-5f);
#pragma unroll
    for (int d = 0; d < 8; d++) {
        float t = (x[d] - mu) * inv * g[d] + b[d];
        x[d] = t > 0.f ? t : 0.f;
    }
}

__global__ void pos_mlp_kernel(
    const float* __restrict__ pp_w, const float* __restrict__ pp_b,
    const float* __restrict__ ln1_g, const float* __restrict__ ln1_b,
    const float* __restrict__ l1_w,  const float* __restrict__ l1_b,
    const float* __restrict__ ln2_g, const float* __restrict__ ln2_b,
    const float* __restrict__ l2_w,  const float* __restrict__ l2_b,
    const float* __restrict__ ln3_g, const float* __restrict__ ln3_b,
    const float* __restrict__ l3_w,  const float* __restrict__ l3_b)
{
    int m = blockIdx.x * blockDim.x + threadIdx.x;
    if (m >= TAB) return;
    float bi = (float)(m / 27 - 13);
    float bj = (float)(m % 27 - 13);
    float h[8], t[8];
#pragma unroll
    for (int d = 0; d < 8; d++) h[d] = bi * pp_w[d] + bj * pp_w[8 + d] + pp_b[d];
    ln_relu8(h, ln1_g, ln1_b);
#pragma unroll
    for (int j = 0; j < 8; j++) {
        float a = l1_b[j];
#pragma unroll
        for (int d = 0; d < 8; d++) a += h[d] * l1_w[d * 8 + j];
        t[j] = a;
    }
    ln_relu8(t, ln2_g, ln2_b);
#pragma unroll
    for (int j = 0; j < 8; j++) {
        float a = l2_b[j];
#pragma unroll
        for (int d = 0; d < 8; d++) a += t[d] * l2_w[d * 8 + j];
        h[j] = a;
    }
    ln_relu8(h, ln3_g, ln3_b);
#pragma unroll
    for (int j = 0; j < NH; j++) {
        float a = l3_b[j];
#pragma unroll
        for (int d = 0; d < 8; d++) a += h[d] * l3_w[d * NH + j];
        g_pos[m * NH + j] = a;
    }
}

// ============================================================
// Kernel: weight prep — transpose to [n][k], bf16 hi/lo split
// ============================================================
__global__ __launch_bounds__(256) void wprep_kernel(
    const float* __restrict__ wq, const float* __restrict__ wkv,
    const float* __restrict__ wproj)
{
    int idx = blockIdx.x * 256 + threadIdx.x;   // 384*128 + 128*128 = 65536
    if (idx < KVN * CDIM) {
        int n = idx >> 7, k = idx & 127;
        float v = (n < 128) ? wq[k * 128 + n] : wkv[k * 256 + (n - 128)];
        __nv_bfloat16 h = __float2bfloat16(v);
        g_wqkv_h[idx] = h;
        g_wqkv_l[idx] = __float2bfloat16(v - __bfloat162float(h));
    } else if (idx < KVN * CDIM + CDIM * CDIM) {
        int j = idx - KVN * CDIM;
        int n = j >> 7, k = j & 127;
        float v = wproj[k * 128 + n];
        __nv_bfloat16 h = __float2bfloat16(v);
        g_wp_h[j] = h;
        g_wp_l[j] = __float2bfloat16(v - __bfloat162float(h));
    }
}

// ============================================================
// Kernel: HMMA GEMM with fused fp32->hi/lo split (unchanged, R4-proven)
// ============================================================
#define TILEB 32768
#define SM_AH 0
#define SM_AL TILEB
#define SM_BH (2 * TILEB)
#define SM_BL (3 * TILEB)
#define GSMEM (4 * TILEB)

__global__ __launch_bounds__(256) void hmma_gemm_kernel(
    int mode, const float* __restrict__ Ain,
    float* __restrict__ Cout, const float* __restrict__ bias)
{
    extern __shared__ char smc[];
    const uint32_t sb = smem_u32(smc);
    const int tid = threadIdx.x;
    const int w = tid >> 5, lane = tid & 31;
    const int m0 = blockIdx.x * 128;

    const float* A = (mode == 0) ? Ain : g_att;
    float* C = (mode == 0) ? g_qkv : Cout;
    const __nv_bfloat16* Bh = (mode == 0) ? g_wqkv_h : g_wp_h;
    const __nv_bfloat16* Bl = (mode == 0) ? g_wqkv_l : g_wp_l;
    const int NB  = (mode == 0) ? 3 : 1;
    const int ldc = (mode == 0) ? KVN : CDIM;
    const bool has_bias = (mode == 1);

    for (int idx = tid; idx < 2048; idx += 256) {
        int row = idx >> 4, c = idx & 15;
        const float* src = A + (size_t)(m0 + row) * CDIM + c * 8;
        float4 v0 = *(const float4*)src;
        float4 v1 = *(const float4*)(src + 4);
        float f[8] = {v0.x, v0.y, v0.z, v0.w, v1.x, v1.y, v1.z, v1.w};
        uint32_t hp[4], lp[4];
#pragma unroll
        for (int q = 0; q < 4; q++) {
            __nv_bfloat16 h0 = __float2bfloat16(f[2 * q]);
            __nv_bfloat16 h1 = __float2bfloat16(f[2 * q + 1]);
            __nv_bfloat162 hh = __halves2bfloat162(h0, h1);
            __nv_bfloat162 ll = __halves2bfloat162(
                __float2bfloat16(f[2 * q] - __bfloat162float(h0)),
                __float2bfloat16(f[2 * q + 1] - __bfloat162float(h1)));
            hp[q] = *(uint32_t*)&hh;
            lp[q] = *(uint32_t*)&ll;
        }
        uint32_t off = swz(row, c);
        *(uint4*)(smc + SM_AH + off) = make_uint4(hp[0], hp[1], hp[2], hp[3]);
        *(uint4*)(smc + SM_AL + off) = make_uint4(lp[0], lp[1], lp[2], lp[3]);
    }

    const int wm = w >> 1;
    const int wn = w & 1;
    const int lrow = lane & 15;
    const int lchunk = lane >> 4;

    for (int nb = 0; nb < NB; nb++) {
        const int n0 = nb * 128;
        __syncthreads();

        for (int idx = tid; idx < 2048; idx += 256) {
            int row = idx >> 4, c = idx & 15;
            size_t gi = (size_t)(n0 + row) * CDIM + c * 8;
            uint4 vh = *(const uint4*)(Bh + gi);
            uint4 vl = *(const uint4*)(Bl + gi);
            uint32_t off = swz(row, c);
            *(uint4*)(smc + SM_BH + off) = vh;
            *(uint4*)(smc + SM_BL + off) = vl;
        }
        __syncthreads();

        float d[2][8][4];
#pragma unroll
        for (int mi = 0; mi < 2; mi++)
#pragma unroll
            for (int ni = 0; ni < 8; ni++)
#pragma unroll
                for (int q = 0; q < 4; q++) d[mi][ni][q] = 0.f;

#pragma unroll 1
        for (int term = 0; term < 3; term++) {
            const uint32_t aBase = sb + ((term == 1) ? SM_AL : SM_AH);
            const uint32_t bBase = sb + ((term == 2) ? SM_BL : SM_BH);
#pragma unroll
            for (int ks = 0; ks < 8; ks++) {
                const int chunk = ks * 2 + lchunk;
                uint32_t a[2][4];
#pragma unroll
                for (int mi = 0; mi < 2; mi++) {
                    int row = wm * 32 + mi * 16 + lrow;
                    ldsm_x4(a[mi][0], a[mi][1], a[mi][2], a[mi][3],
                            aBase + swz(row, chunk));
                }
                uint32_t b[8][2];
#pragma unroll
                for (int np = 0; np < 4; np++) {
                    int row = wn * 64 + np * 16 + lrow;
                    uint32_t r0, r1, r2, r3;
                    ldsm_x4(r0, r1, r2, r3, bBase + swz(row, chunk));
                    b[2 * np][0] = r0; b[2 * np + 1][0] = r1;
                    b[2 * np][1] = r2; b[2 * np + 1][1] = r3;
                }
#pragma unroll
                for (int mi = 0; mi < 2; mi++)
#pragma unroll
                    for (int ni = 0; ni < 8; ni++)
                        mma16816(d[mi][ni], a[mi], b[ni]);
            }
        }

        const int mrow = m0 + wm * 32 + (lane >> 2);
        const int ncol = n0 + wn * 64 + (lane & 3) * 2;
#pragma unroll
        for (int mi = 0; mi < 2; mi++) {
#pragma unroll
            for (int ni = 0; ni < 8; ni++) {
                float b0 = 0.f, b1 = 0.f;
                if (has_bias) {
                    b0 = bias[ncol + ni * 8];
                    b1 = bias[ncol + ni * 8 + 1];
                }
                float* p0 = C + (size_t)(mrow + mi * 16) * ldc + ncol + ni * 8;
                float* p1 = C + (size_t)(mrow + mi * 16 + 8) * ldc + ncol + ni * 8;
                *(float2*)p0 = make_float2(d[mi][ni][0] + b0, d[mi][ni][1] + b1);
                *(float2*)p1 = make_float2(d[mi][ni][2] + b0, d[mi][ni][3] + b1);
            }
        }
    }
}

// ============================================================
// HMMA flash attention: one CTA per (b,h), 8 warps
//   Q/K hi/lo: [208 rows][32 d] bf16, row stride 80 B (conflict-free ldmatrix)
//   Vt hi/lo:  [32 d][208 kk] bf16, row stride 432 B
//   strip = 16 q-rows per warp; softmax over 208 cols in 2 halves (112+96)
// ============================================================
#define AQH 0
#define AQL 16640
#define AKH 33280
#define AKL 49920
#define AVTH 66560
#define AVTL 80384
#define ASPOS 94208
#define ACOLC (ASPOS + TAB * NH * 4)      // 105872
#define ATTN_SMEM (ACOLC + 208 * 4)       // 106704

template<int NSTART, int NT>
__device__ __forceinline__ void half_pass(
    uint32_t qh, uint32_t ql, uint32_t kh, uint32_t kl,
    uint32_t vth, uint32_t vtl,
    const float* __restrict__ spos, const int* __restrict__ colC,
    int m0, int h, int R0, int R1, int lane,
    float o[4][4], float& mo0, float& mo1, float& sum0, float& sum1)
{
    const int lrow = lane & 15, lhalf = lane >> 4;
    float S[NT][4];
#pragma unroll
    for (int j = 0; j < NT; j++)
#pragma unroll
        for (int q = 0; q < 4; q++) S[j][q] = 0.f;

    // ---- QK^T, 3 split terms ----
#pragma unroll
    for (int term = 0; term < 3; term++) {
        uint32_t Ab = (term == 1) ? ql : qh;
        uint32_t Bb = (term == 2) ? kl : kh;
#pragma unroll
        for (int k0 = 0; k0 < 2; k0++) {
            uint32_t a[4];
            ldsm_x4(a[0], a[1], a[2], a[3],
                    Ab + (uint32_t)((m0 + lrow) * 80 + (k0 * 2 + lhalf) * 16));
#pragma unroll
            for (int np = 0; np < NT / 2; np++) {
                uint32_t r0, r1, r2, r3;
                ldsm_x4(r0, r1, r2, r3,
                        Bb + (uint32_t)(((NSTART + 2 * np) * 8 + lrow) * 80
                                        + (k0 * 2 + lhalf) * 16));
                uint32_t b0[2] = {r0, r2}, b1[2] = {r1, r3};
                mma16816(S[2 * np], a, b0);
                mma16816(S[2 * np + 1], a, b1);
            }
        }
    }

    // ---- bias + mask + row max ----
    float ml0 = -1e30f, ml1 = -1e30f;
#pragma unroll
    for (int j = 0; j < NT; j++) {
        int c0 = (NSTART + j) * 8 + (lane & 3) * 2;
#pragma unroll
        for (int e = 0; e < 2; e++) {
            int c = c0 + e;
            if (c < NQ) {
                int C4 = colC[c];
                S[j][e]     += spos[((R0 - C4) << 2) + h];
                S[j][2 + e] += spos[((R1 - C4) << 2) + h];
            } else {
                S[j][e] = -1e30f;
                S[j][2 + e] = -1e30f;
            }
        }
        ml0 = fmaxf(ml0, fmaxf(S[j][0], S[j][1]));
        ml1 = fmaxf(ml1, fmaxf(S[j][2], S[j][3]));
    }
    ml0 = fmaxf(ml0, __shfl_xor_sync(0xffffffffu, ml0, 1));
    ml0 = fmaxf(ml0, __shfl_xor_sync(0xffffffffu, ml0, 2));
    ml1 = fmaxf(ml1, __shfl_xor_sync(0xffffffffu, ml1, 1));
    ml1 = fmaxf(ml1, __shfl_xor_sync(0xffffffffu, ml1, 2));
    float mn0 = fmaxf(mo0, ml0), mn1 = fmaxf(mo1, ml1);
    float f0 = __expf(mo0 - mn0), f1 = __expf(mo1 - mn1);
    mo0 = mn0; mo1 = mn1;
    sum0 *= f0; sum1 *= f1;
#pragma unroll
    for (int n = 0; n < 4; n++) {
        o[n][0] *= f0; o[n][1] *= f0;
        o[n][2] *= f1; o[n][3] *= f1;
    }

    // ---- P = exp(S-m) -> bf16 hi/lo frags; PV 3 split terms ----
#pragma unroll
    for (int t = 0; t < NT / 2; t++) {
        uint32_t ah[4], al[4];
#pragma unroll
        for (int jj = 0; jj < 2; jj++) {
            int j = 2 * t + jj;
            float p0 = __expf(S[j][0] - mn0);
            float p1 = __expf(S[j][1] - mn0);
            float p2 = __expf(S[j][2] - mn1);
            float p3 = __expf(S[j][3] - mn1);
            sum0 += p0 + p1; sum1 += p2 + p3;
            __nv_bfloat16 h0 = __float2bfloat16(p0), h1 = __float2bfloat16(p1);
            __nv_bfloat16 h2 = __float2bfloat16(p2), h3 = __float2bfloat16(p3);
            __nv_bfloat162 H0 = __halves2bfloat162(h0, h1);
            __nv_bfloat162 H1 = __halves2bfloat162(h2, h3);
            ah[2 * jj]     = *(uint32_t*)&H0;
            ah[2 * jj + 1] = *(uint32_t*)&H1;
            __nv_bfloat162 L0 = __halves2bfloat162(
                __float2bfloat16(p0 - __bfloat162float(h0)),
                __float2bfloat16(p1 - __bfloat162float(h1)));
            __nv_bfloat162 L1 = __halves2bfloat162(
                __float2bfloat16(p2 - __bfloat162float(h2)),
                __float2bfloat16(p3 - __bfloat162float(h3)));
            al[2 * jj]     = *(uint32_t*)&L0;
            al[2 * jj + 1] = *(uint32_t*)&L1;
        }
        int kchunk = NSTART + 2 * t + lhalf;
#pragma unroll
        for (int np = 0; np < 2; np++) {
            uint32_t r0, r1, r2, r3;
            ldsm_x4(r0, r1, r2, r3,
                    vth + (uint32_t)((np * 16 + lrow) * 432 + kchunk * 16));
            {
                uint32_t b0[2] = {r0, r2}, b1[2] = {r1, r3};
                mma16816(o[2 * np], ah, b0); mma16816(o[2 * np + 1], ah, b1);
                mma16816(o[2 * np], al, b0); mma16816(o[2 * np + 1], al, b1);
            }
            ldsm_x4(r0, r1, r2, r3,
                    vtl + (uint32_t)((np * 16 + lrow) * 432 + kchunk * 16));
            {
                uint32_t b0[2] = {r0, r2}, b1[2] = {r1, r3};
                mma16816(o[2 * np], ah, b0); mma16816(o[2 * np + 1], ah, b1);
            }
        }
    }
}

__global__ __launch_bounds__(256, 2) void fattn_kernel()
{
    extern __shared__ char smb[];
    const uint32_t sb = smem_u32(smb);
    float* spos = (float*)(smb + ASPOS);
    int* colC = (int*)(smb + ACOLC);
    const int b = blockIdx.x, h = blockIdx.y;
    const int tid = threadIdx.x;

    // ---- stage q*scale/k/v as bf16 hi/lo (+ Vt transposed) ----
    const float* base = g_qkv + (size_t)b * NQ * KVN + h * HD;
    for (int idx = tid; idx < 208 * 32; idx += 256) {
        int n = idx >> 5, d = idx & 31;
        float qv = 0.f, kv = 0.f, vv = 0.f;
        if (n < NQ) {
            const float* row = base + (size_t)n * KVN;
            qv = row[d] * SCALE;
            kv = row[128 + d];
            vv = row[256 + d];
        }
        __nv_bfloat16 qhb = __float2bfloat16(qv);
        __nv_bfloat16 qlb = __float2bfloat16(qv - __bfloat162float(qhb));
        __nv_bfloat16 khb = __float2bfloat16(kv);
        __nv_bfloat16 klb = __float2bfloat16(kv - __bfloat162float(khb));
        __nv_bfloat16 vhb = __float2bfloat16(vv);
        __nv_bfloat16 vlb = __float2bfloat16(vv - __bfloat162float(vhb));
        *(__nv_bfloat16*)(smb + AQH + n * 80 + d * 2) = qhb;
        *(__nv_bfloat16*)(smb + AQL + n * 80 + d * 2) = qlb;
        *(__nv_bfloat16*)(smb + AKH + n * 80 + d * 2) = khb;
        *(__nv_bfloat16*)(smb + AKL + n * 80 + d * 2) = klb;
        *(__nv_bfloat16*)(smb + AVTH + d * 432 + n * 2) = vhb;
        *(__nv_bfloat16*)(smb + AVTL + d * 432 + n * 2) = vlb;
    }
    for (int i = tid; i < TAB * NH; i += 256) spos[i] = g_pos[i];
    for (int c = tid; c < 208; c += 256)
        colC[c] = (c < NQ) ? (c / 14) * 27 + (c % 14) : 0;
    __syncthreads();

    const int w = tid >> 5, lane = tid & 31;
    for (int s = w; s < 13; s += 8) {
        const int m0 = s * 16;
        const int row0 = m0 + (lane >> 2), row1 = row0 + 8;
        const int rc0 = min(row0, NQ - 1), rc1 = min(row1, NQ - 1);
        const int R0 = (rc0 / 14) * 27 + rc0 % 14 + 364;
        const int R1 = (rc1 / 14) * 27 + rc1 % 14 + 364;

        float o[4][4];
#pragma unroll
        for (int n = 0; n < 4; n++)
#pragma unroll
            for (int q = 0; q < 4; q++) o[n][q] = 0.f;
        float mo0 = -1e30f, mo1 = -1e30f, sum0 = 0.f, sum1 = 0.f;

        half_pass<0, 14>(sb + AQH, sb + AQL, sb + AKH, sb + AKL,
                         sb + AVTH, sb + AVTL, spos, colC,
                         m0, h, R0, R1, lane, o, mo0, mo1, sum0, sum1);
        half_pass<14, 12>(sb + AQH, sb + AQL, sb + AKH, sb + AKL,
                          sb + AVTH, sb + AVTL, spos, colC,
                          m0, h, R0, R1, lane, o, mo0, mo1, sum0, sum1);

        sum0 += __shfl_xor_sync(0xffffffffu, sum0, 1);
        sum0 += __shfl_xor_sync(0xffffffffu, sum0, 2);
        sum1 += __shfl_xor_sync(0xffffffffu, sum1, 1);
        sum1 += __shfl_xor_sync(0xffffffffu, sum1, 2);
        float i0 = 1.f / sum0, i1 = 1.f / sum1;

#pragma unroll
        for (int n = 0; n < 4; n++) {
            int d0 = n * 8 + (lane & 3) * 2;
            if (row0 < NQ)
                *(float2*)&g_att[((size_t)b * NQ + row0) * CDIM + h * HD + d0] =
                    make_float2(o[n][0] * i0, o[n][1] * i0);
            if (row1 < NQ)
                *(float2*)&g_att[((size_t)b * NQ + row1) * CDIM + h * HD + d0] =
                    make_float2(o[n][2] * i1, o[n][3] * i1);
        }
    }
}

// ============================================================
// launch
// ============================================================
extern "C" void kernel_launch(void* const* d_in, const int* in_sizes, int n_in,
                              void* d_out, int out_size)
{
    const float* x     = (const float*)d_in[0];
    const float* wq    = (const float*)d_in[1];
    const float* wkv   = (const float*)d_in[2];
    const float* wproj = (const float*)d_in[3];
    const float* bproj = (const float*)d_in[4];
    const float* pp_w  = (const float*)d_in[5];
    const float* pp_b  = (const float*)d_in[6];
    const float* ln1_g = (const float*)d_in[7];
    const float* ln1_b = (const float*)d_in[8];
    const float* l1_w  = (const float*)d_in[9];
    const float* l1_b  = (const float*)d_in[10];
    const float* ln2_g = (const float*)d_in[11];
    const float* ln2_b = (const float*)d_in[12];
    const float* l2_w  = (const float*)d_in[13];
    const float* l2_b  = (const float*)d_in[14];
    const float* ln3_g = (const float*)d_in[15];
    const float* ln3_b = (const float*)d_in[16];
    const float* l3_w  = (const float*)d_in[17];
    const float* l3_b  = (const float*)d_in[18];
    float* out = (float*)d_out;

    cudaFuncSetAttribute(hmma_gemm_kernel,
                         cudaFuncAttributeMaxDynamicSharedMemorySize, GSMEM);
    cudaFuncSetAttribute(fattn_kernel,
                         cudaFuncAttributeMaxDynamicSharedMemorySize, ATTN_SMEM);

    pos_mlp_kernel<<<3, 256>>>(pp_w, pp_b, ln1_g, ln1_b, l1_w, l1_b,
                               ln2_g, ln2_b, l2_w, l2_b,
                               ln3_g, ln3_b, l3_w, l3_b);

    wprep_kernel<<<256, 256>>>(wq, wkv, wproj);

    // QKV: x @ [wq|wkv] -> g_qkv
    hmma_gemm_kernel<<<MTOT / 128, 256, GSMEM>>>(0, x, nullptr, nullptr);

    // flash attention -> g_att
    fattn_kernel<<<dim3(BATCH, NH), 256, ATTN_SMEM>>>();

    // Proj: g_att @ wproj + bproj -> out
    hmma_gemm_kernel<<<MTOT / 128, 256, GSMEM>>>(1, nullptr, out, bproj);
}